// round 2
// baseline (speedup 1.0000x reference)
#include <cuda_runtime.h>
#include <cuda_bf16.h>

// Problem constants (fixed shapes from reference setup_inputs)
#define IMG_H 544
#define IMG_W 960
#define OUT_H 136
#define OUT_W 240

// Tile config: each block produces TW x TH output (downsampled) pixels
#define TW 24
#define TH 8
#define MW (TW*4)          // 96  mag tile width
#define MH (TH*4)          // 32  mag tile height
#define GSW (MW+2)         // 98  gray_smooth region width  (sobel halo 1)
#define GSH (MH+2)         // 34  gray_smooth region height
#define GRW (MW+6)         // 102 gray region width  (blur halo 2 more + sobel halo)
#define GRH (MH+6)         // 38  gray region height
#define GRW_P 104          // padded stride
#define HBW GSW            // 98  horizontal-blur width
#define HBH GRH            // 38  horizontal-blur height (needs vertical halo)
#define HBW_P 100

// Normalized 1D Gaussian, k=5, sigma=1.5 (double-precision derived)
#define GW0 0.120078385f
#define GW1 0.233880757f
#define GW2 0.292081718f

__device__ __forceinline__ int reflect_idx(int i, int n) {
    if (i < 0) i = -i;
    if (i >= n) i = 2 * n - 2 - i;
    return i;
}

__global__ __launch_bounds__(256)
void EdgeGuidance_47313359733145_kernel(const float* __restrict__ in,
                                        float* __restrict__ out)
{
    const int bx = blockIdx.x;   // tile x (0..9)
    const int by = blockIdx.y;   // tile y (0..16)
    const int b  = blockIdx.z;   // batch

    const int mx0 = bx * MW;     // mag-space origin
    const int my0 = by * MH;

    __shared__ float sGray[GRH * GRW_P];   // 38*104*4 = 15808 B
    __shared__ float sH[HBH * HBW_P];      // 38*100*4 = 15200 B
    float* sGS = sGray;                    // reuse gray buffer for gray_smooth (stride GRW_P)

    const int tid = threadIdx.x;
    const float* pr = in + (size_t)b * 3 * IMG_H * IMG_W;
    const float* pg = pr + IMG_H * IMG_W;
    const float* pb = pg + IMG_H * IMG_W;

    // ---- Stage 1: RGB -> gray into SMEM (reflect-padded halo of 3) ----
    #pragma unroll 1
    for (int i = tid; i < GRH * GRW; i += 256) {
        int y = i / GRW;
        int x = i - y * GRW;
        int iy = reflect_idx(my0 - 3 + y, IMG_H);
        int ix = reflect_idx(mx0 - 3 + x, IMG_W);
        int o = iy * IMG_W + ix;
        float g = 0.2989f * pr[o] + 0.587f * pg[o] + 0.114f * pb[o];
        sGray[y * GRW_P + x] = g;
    }
    __syncthreads();

    // ---- Stage 2: horizontal Gaussian -> sH ----
    #pragma unroll 1
    for (int i = tid; i < HBH * HBW; i += 256) {
        int y = i / HBW;
        int x = i - y * HBW;
        const float* r = &sGray[y * GRW_P + x];
        sH[y * HBW_P + x] = GW0 * r[0] + GW1 * r[1] + GW2 * r[2]
                          + GW1 * r[3] + GW0 * r[4];
    }
    __syncthreads();

    // ---- Stage 3: vertical Gaussian -> sGS (aliases sGray; zero outside image) ----
    #pragma unroll 1
    for (int i = tid; i < GSH * GSW; i += 256) {
        int y = i / GSW;
        int x = i - y * GSW;
        int gyc = my0 - 1 + y;        // global coords of this gray_smooth sample
        int gxc = mx0 - 1 + x;
        float v;
        if (gyc < 0 || gyc >= IMG_H || gxc < 0 || gxc >= IMG_W) {
            v = 0.0f;                 // sobel zero padding
        } else {
            const float* c = &sH[y * HBW_P + x];
            v = GW0 * c[0]
              + GW1 * c[1 * HBW_P]
              + GW2 * c[2 * HBW_P]
              + GW1 * c[3 * HBW_P]
              + GW0 * c[4 * HBW_P];
        }
        sGS[y * GRW_P + x] = v;
    }
    __syncthreads();

    // ---- Stage 4: sobel + magnitude + 4x4 avg pool + sigmoid^2 ----
    if (tid < TW * TH) {
        int ty = tid / TW;
        int tx = tid - ty * TW;
        // 6x6 gray_smooth patch: rows 4*ty .. 4*ty+5, cols 4*tx .. 4*tx+5
        const float* base = &sGS[(4 * ty) * GRW_P + 4 * tx];

        float r0[6], r1[6], r2[6];
        #pragma unroll
        for (int c = 0; c < 6; c++) r0[c] = base[c];
        #pragma unroll
        for (int c = 0; c < 6; c++) r1[c] = base[GRW_P + c];

        float sum = 0.0f;
        #pragma unroll
        for (int r = 1; r <= 4; r++) {
            #pragma unroll
            for (int c = 0; c < 6; c++) r2[c] = base[(r + 1) * GRW_P + c];

            // column sums (1,2,1) vertically
            float cv[6];
            #pragma unroll
            for (int c = 0; c < 6; c++) cv[c] = r0[c] + 2.0f * r1[c] + r2[c];

            #pragma unroll
            for (int c = 1; c <= 4; c++) {
                float gx = cv[c + 1] - cv[c - 1];
                float gy = (r2[c - 1] + 2.0f * r2[c] + r2[c + 1])
                         - (r0[c - 1] + 2.0f * r0[c] + r0[c + 1]);
                sum += sqrtf(gx * gx + gy * gy + 1e-6f);
            }
            #pragma unroll
            for (int c = 0; c < 6; c++) { r0[c] = r1[c]; r1[c] = r2[c]; }
        }

        float down = sum * (1.0f / 16.0f);
        float s = 1.0f / (1.0f + expf(-5.0f * (down - 0.2f)));
        int oy = by * TH + ty;
        int ox = bx * TW + tx;
        out[((size_t)b * OUT_H + oy) * OUT_W + ox] = s * s;
    }
}

extern "C" void kernel_launch(void* const* d_in, const int* in_sizes, int n_in,
                              void* d_out, int out_size)
{
    const float* in = (const float*)d_in[0];
    float* out = (float*)d_out;
    int B = in_sizes[0] / (3 * IMG_H * IMG_W);   // 16

    dim3 grid(OUT_W / TW, OUT_H / TH, B);        // (10, 17, 16)
    EdgeGuidance_47313359733145_kernel<<<grid, 256>>>(in, out);
}

// round 3
// speedup vs baseline: 1.6752x; 1.6752x over previous
#include <cuda_runtime.h>
#include <cuda_bf16.h>

// Fixed problem shapes
#define IMG_H 544
#define IMG_W 960
#define OUT_H 136
#define OUT_W 240

// Tile: 30x8 output pixels per block -> 120x32 mag region
#define TW 30
#define TH 8
#define MW 120            // mag tile width
#define MH 32             // mag tile height
#define GRH 38            // gray rows   (MH + 6)
#define GSH 34            // gray_smooth rows (MH + 2)
#define STRIDE 128        // float stride for both smem buffers (32 float4)

// Normalized 1D Gaussian, k=5, sigma=1.5
#define GW0 0.120078385f
#define GW1 0.233880757f
#define GW2 0.292081718f

__device__ __forceinline__ int reflect_idx(int i, int n) {
    if (i < 0) i = -i;
    if (i >= n) i = 2 * n - 2 - i;
    return i;
}

__global__ __launch_bounds__(256)
void EdgeGuidance_47313359733145_kernel(const float* __restrict__ in,
                                        float* __restrict__ out)
{
    const int bx = blockIdx.x;            // 0..7
    const int by = blockIdx.y;            // 0..16
    const int b  = blockIdx.z;            // 0..15

    const int mx0 = bx * MW;              // mag-space tile origin
    const int my0 = by * MH;

    // sA: gray (38x128), later reused for gray_smooth (34x128). +4 pad for tap guard.
    __shared__ float sA[GRH * STRIDE + 4];
    __shared__ float sB[GRH * STRIDE];    // horizontal blur

    const int tid = threadIdx.x;
    const float* __restrict__ pr = in + (size_t)b * 3 * IMG_H * IMG_W;
    const float* __restrict__ pg = pr + IMG_H * IMG_W;
    const float* __restrict__ pb = pg + IMG_H * IMG_W;

    // ---------- Stage 1: RGB -> gray, vectorized (gray local x = global - (mx0-4)) ----------
    // 38 rows x 32 float4 = 1216 items
    #pragma unroll 1
    for (int i = tid; i < GRH * 32; i += 256) {
        const int y  = i >> 5;
        const int j  = i & 31;
        const int gy = reflect_idx(my0 - 3 + y, IMG_H);
        const int gx0 = mx0 - 4 + (j << 2);

        float4 r4, g4, b4;
        if (gx0 >= 0 && gx0 + 3 < IMG_W) {
            const int o = gy * IMG_W + gx0;
            r4 = *reinterpret_cast<const float4*>(pr + o);
            g4 = *reinterpret_cast<const float4*>(pg + o);
            b4 = *reinterpret_cast<const float4*>(pb + o);
        } else {
            float rr[4], gg[4], bb[4];
            #pragma unroll
            for (int e = 0; e < 4; e++) {
                int gx = reflect_idx(gx0 + e, IMG_W);
                int o = gy * IMG_W + gx;
                rr[e] = pr[o]; gg[e] = pg[o]; bb[e] = pb[o];
            }
            r4 = make_float4(rr[0], rr[1], rr[2], rr[3]);
            g4 = make_float4(gg[0], gg[1], gg[2], gg[3]);
            b4 = make_float4(bb[0], bb[1], bb[2], bb[3]);
        }
        float4 gr;
        gr.x = fmaf(0.2989f, r4.x, fmaf(0.587f, g4.x, 0.114f * b4.x));
        gr.y = fmaf(0.2989f, r4.y, fmaf(0.587f, g4.y, 0.114f * b4.y));
        gr.z = fmaf(0.2989f, r4.z, fmaf(0.587f, g4.z, 0.114f * b4.z));
        gr.w = fmaf(0.2989f, r4.w, fmaf(0.587f, g4.w, 0.114f * b4.w));
        *reinterpret_cast<float4*>(&sA[(y << 7) + (j << 2)]) = gr;
    }
    __syncthreads();

    // ---------- Stage 2: horizontal Gaussian -> sB ----------
    // output o covers gs x = mx0-1+o; sB[o] = sum gw[k]*gray[o+1+k]
    // 38 rows x 31 vec4 (o = 0..123)
    #pragma unroll 1
    for (int i = tid; i < GRH * 32; i += 256) {
        const int y = i >> 5;
        const int j = i & 31;
        if (j >= 31) continue;
        const float* g = &sA[(y << 7) + (j << 2)];
        const float4 A = *reinterpret_cast<const float4*>(g);
        const float4 Bv = *reinterpret_cast<const float4*>(g + 4);
        const float c0 = (j < 30) ? g[8] : 0.0f;   // tap only used by out3; j==30's out3 unused

        float4 o4;
        o4.x = fmaf(GW0, A.y, fmaf(GW1, A.z, fmaf(GW2, A.w, fmaf(GW1, Bv.x, GW0 * Bv.y))));
        o4.y = fmaf(GW0, A.z, fmaf(GW1, A.w, fmaf(GW2, Bv.x, fmaf(GW1, Bv.y, GW0 * Bv.z))));
        o4.z = fmaf(GW0, A.w, fmaf(GW1, Bv.x, fmaf(GW2, Bv.y, fmaf(GW1, Bv.z, GW0 * Bv.w))));
        o4.w = fmaf(GW0, Bv.x, fmaf(GW1, Bv.y, fmaf(GW2, Bv.z, fmaf(GW1, Bv.w, GW0 * c0))));
        *reinterpret_cast<float4*>(&sB[(y << 7) + (j << 2)]) = o4;
    }
    __syncthreads();

    // ---------- Stage 3: vertical Gaussian -> sA (gray_smooth, zero outside image) ----------
    // gs[y][x] at global (my0-1+y, mx0-1+x); 34 rows x 31 vec4
    #pragma unroll 1
    for (int i = tid; i < GSH * 32; i += 256) {
        const int y = i >> 5;
        const int j = i & 31;
        if (j >= 31) continue;
        const int gy = my0 - 1 + y;
        float4 v = make_float4(0.f, 0.f, 0.f, 0.f);
        if (gy >= 0 && gy < IMG_H) {
            const float* c = &sB[(y << 7) + (j << 2)];
            const float4 t0 = *reinterpret_cast<const float4*>(c);
            const float4 t1 = *reinterpret_cast<const float4*>(c + STRIDE);
            const float4 t2 = *reinterpret_cast<const float4*>(c + 2 * STRIDE);
            const float4 t3 = *reinterpret_cast<const float4*>(c + 3 * STRIDE);
            const float4 t4 = *reinterpret_cast<const float4*>(c + 4 * STRIDE);
            v.x = fmaf(GW0, t0.x, fmaf(GW1, t1.x, fmaf(GW2, t2.x, fmaf(GW1, t3.x, GW0 * t4.x))));
            v.y = fmaf(GW0, t0.y, fmaf(GW1, t1.y, fmaf(GW2, t2.y, fmaf(GW1, t3.y, GW0 * t4.y))));
            v.z = fmaf(GW0, t0.z, fmaf(GW1, t1.z, fmaf(GW2, t2.z, fmaf(GW1, t3.z, GW0 * t4.z))));
            v.w = fmaf(GW0, t0.w, fmaf(GW1, t1.w, fmaf(GW2, t2.w, fmaf(GW1, t3.w, GW0 * t4.w))));
            // x boundary (sobel zero padding): mask out-of-image columns
            const int gx = mx0 - 1 + (j << 2);
            if (gx < 0 || gx >= IMG_W)           v.x = 0.f;
            if (gx + 1 < 0 || gx + 1 >= IMG_W)   v.y = 0.f;
            if (gx + 2 >= IMG_W)                 v.z = 0.f;
            if (gx + 3 >= IMG_W)                 v.w = 0.f;
        }
        *reinterpret_cast<float4*>(&sA[(y << 7) + (j << 2)]) = v;
    }
    __syncthreads();

    // ---------- Stage 4: sobel + magnitude + 4x4 avg pool + sigmoid^2 ----------
    if (tid < TW * TH) {
        const int ty = tid / TW;
        const int tx = tid - ty * TW;
        const float* base = &sA[((ty << 2) << 7) + (tx << 2)];

        float r0[6], r1[6], r2[6];
        {
            float4 L = *reinterpret_cast<const float4*>(base);
            float4 R = *reinterpret_cast<const float4*>(base + 4);
            r0[0]=L.x; r0[1]=L.y; r0[2]=L.z; r0[3]=L.w; r0[4]=R.x; r0[5]=R.y;
            L = *reinterpret_cast<const float4*>(base + STRIDE);
            R = *reinterpret_cast<const float4*>(base + STRIDE + 4);
            r1[0]=L.x; r1[1]=L.y; r1[2]=L.z; r1[3]=L.w; r1[4]=R.x; r1[5]=R.y;
        }

        float sum = 0.0f;
        #pragma unroll
        for (int r = 1; r <= 4; r++) {
            const float4 L = *reinterpret_cast<const float4*>(base + (r + 1) * STRIDE);
            const float4 R = *reinterpret_cast<const float4*>(base + (r + 1) * STRIDE + 4);
            r2[0]=L.x; r2[1]=L.y; r2[2]=L.z; r2[3]=L.w; r2[4]=R.x; r2[5]=R.y;

            float cv[6];
            #pragma unroll
            for (int c = 0; c < 6; c++) cv[c] = r0[c] + 2.0f * r1[c] + r2[c];

            #pragma unroll
            for (int c = 1; c <= 4; c++) {
                const float gx = cv[c + 1] - cv[c - 1];
                const float gy = (r2[c - 1] + 2.0f * r2[c] + r2[c + 1])
                               - (r0[c - 1] + 2.0f * r0[c] + r0[c + 1]);
                sum += sqrtf(fmaf(gx, gx, fmaf(gy, gy, 1e-6f)));
            }
            #pragma unroll
            for (int c = 0; c < 6; c++) { r0[c] = r1[c]; r1[c] = r2[c]; }
        }

        const float down = sum * (1.0f / 16.0f);
        const float s = 1.0f / (1.0f + expf(-5.0f * (down - 0.2f)));
        const int oy = by * TH + ty;
        const int ox = bx * TW + tx;
        out[((size_t)b * OUT_H + oy) * OUT_W + ox] = s * s;
    }
}

extern "C" void kernel_launch(void* const* d_in, const int* in_sizes, int n_in,
                              void* d_out, int out_size)
{
    const float* in = (const float*)d_in[0];
    float* out = (float*)d_out;
    int B = in_sizes[0] / (3 * IMG_H * IMG_W);   // 16

    dim3 grid(OUT_W / TW, OUT_H / TH, B);        // (8, 17, 16) = 2176 blocks
    EdgeGuidance_47313359733145_kernel<<<grid, 256>>>(in, out);
}

// round 4
// speedup vs baseline: 1.8499x; 1.1043x over previous
#include <cuda_runtime.h>
#include <cuda_bf16.h>

// Fixed problem shapes
#define IMG_H 544
#define IMG_W 960
#define OUT_H 136
#define OUT_W 240

// Tile: 30x8 output pixels per block -> 120x32 mag region
#define TW 30
#define TH 8
#define MW 120
#define MH 32
#define GRH 38            // gray / h-blur rows (MH + 6)
#define GSH 34            // gray_smooth rows  (MH + 2)
#define SW 124            // smem stride in floats (31 float4)

// Normalized 1D Gaussian, k=5, sigma=1.5
#define GW0 0.120078385f
#define GW1 0.233880757f
#define GW2 0.292081718f

__device__ __forceinline__ int reflect_idx(int i, int n) {
    if (i < 0) i = -i;
    if (i >= n) i = 2 * n - 2 - i;
    return i;
}

__device__ __forceinline__ float sqrt_approx(float x) {
    float r;
    asm("sqrt.approx.f32 %0, %1;" : "=f"(r) : "f"(x));
    return r;
}

__global__ __launch_bounds__(256, 6)
void EdgeGuidance_47313359733145_kernel(const float* __restrict__ in,
                                        float* __restrict__ out)
{
    const int bx = blockIdx.x;            // 0..7
    const int by = blockIdx.y;            // 0..16
    const int b  = blockIdx.z;            // 0..15

    const int mx0 = bx * MW;
    const int my0 = by * MH;

    __shared__ float sH[GRH * SW];        // horizontal blur  (38x124)
    __shared__ float sG[GSH * SW];        // gray_smooth      (34x124)

    const int tid = threadIdx.x;
    const float* __restrict__ pr = in + (size_t)b * 3 * IMG_H * IMG_W;
    const float* __restrict__ pg = pr + IMG_H * IMG_W;
    const float* __restrict__ pb = pg + IMG_H * IMG_W;

    // ---- Stage 1+2 fused: RGB -> gray (registers) -> h-blur via warp shuffle ----
    // Each warp iteration handles one full gray row: lane = vec-column j (0..31),
    // gray local x = 4j covering global mx0-4+4j. Output h-blur vec j (j<31).
    #pragma unroll 1
    for (int i = tid; i < GRH * 32; i += 256) {
        const int y  = i >> 5;
        const int j  = i & 31;                        // == lane id
        const int gy = reflect_idx(my0 - 3 + y, IMG_H);
        const int gx0 = mx0 - 4 + (j << 2);

        float4 r4, g4, b4;
        if (gx0 >= 0 && gx0 + 3 < IMG_W) {
            const int o = gy * IMG_W + gx0;
            r4 = *reinterpret_cast<const float4*>(pr + o);
            g4 = *reinterpret_cast<const float4*>(pg + o);
            b4 = *reinterpret_cast<const float4*>(pb + o);
        } else {
            float rr[4], gg[4], bb[4];
            #pragma unroll
            for (int e = 0; e < 4; e++) {
                int gx = reflect_idx(gx0 + e, IMG_W);
                int o = gy * IMG_W + gx;
                rr[e] = pr[o]; gg[e] = pg[o]; bb[e] = pb[o];
            }
            r4 = make_float4(rr[0], rr[1], rr[2], rr[3]);
            g4 = make_float4(gg[0], gg[1], gg[2], gg[3]);
            b4 = make_float4(bb[0], bb[1], bb[2], bb[3]);
        }
        float4 A;
        A.x = fmaf(0.2989f, r4.x, fmaf(0.587f, g4.x, 0.114f * b4.x));
        A.y = fmaf(0.2989f, r4.y, fmaf(0.587f, g4.y, 0.114f * b4.y));
        A.z = fmaf(0.2989f, r4.z, fmaf(0.587f, g4.z, 0.114f * b4.z));
        A.w = fmaf(0.2989f, r4.w, fmaf(0.587f, g4.w, 0.114f * b4.w));

        // Neighbor gray vec (lane j+1) and first element of lane j+2
        const unsigned m = 0xffffffffu;
        const float Bx = __shfl_down_sync(m, A.x, 1);
        const float By = __shfl_down_sync(m, A.y, 1);
        const float Bz = __shfl_down_sync(m, A.z, 1);
        const float Bw = __shfl_down_sync(m, A.w, 1);
        const float C0 = __shfl_down_sync(m, A.x, 2);   // garbage at lane30: lands in unused x=123

        if (j < 31) {
            float4 o4;
            o4.x = fmaf(GW0, A.y, fmaf(GW1, A.z, fmaf(GW2, A.w, fmaf(GW1, Bx, GW0 * By))));
            o4.y = fmaf(GW0, A.z, fmaf(GW1, A.w, fmaf(GW2, Bx, fmaf(GW1, By, GW0 * Bz))));
            o4.z = fmaf(GW0, A.w, fmaf(GW1, Bx, fmaf(GW2, By, fmaf(GW1, Bz, GW0 * Bw))));
            o4.w = fmaf(GW0, Bx, fmaf(GW1, By, fmaf(GW2, Bz, fmaf(GW1, Bw, GW0 * C0))));
            *reinterpret_cast<float4*>(&sH[y * SW + (j << 2)]) = o4;
        }
    }
    __syncthreads();

    // ---- Stage 3: vertical Gaussian, two rows per thread (6 loads -> 2 outputs) ----
    #pragma unroll 1
    for (int i = tid; i < 17 * 32; i += 256) {
        const int p = i >> 5;                 // gs row pair: rows 2p, 2p+1
        const int j = i & 31;
        if (j >= 31) continue;
        const float* c = &sH[(p << 1) * SW + (j << 2)];
        const float4 t0 = *reinterpret_cast<const float4*>(c);
        const float4 t1 = *reinterpret_cast<const float4*>(c + SW);
        const float4 t2 = *reinterpret_cast<const float4*>(c + 2 * SW);
        const float4 t3 = *reinterpret_cast<const float4*>(c + 3 * SW);
        const float4 t4 = *reinterpret_cast<const float4*>(c + 4 * SW);
        const float4 t5 = *reinterpret_cast<const float4*>(c + 5 * SW);

        float4 v0, v1;
        v0.x = fmaf(GW0, t0.x, fmaf(GW1, t1.x, fmaf(GW2, t2.x, fmaf(GW1, t3.x, GW0 * t4.x))));
        v0.y = fmaf(GW0, t0.y, fmaf(GW1, t1.y, fmaf(GW2, t2.y, fmaf(GW1, t3.y, GW0 * t4.y))));
        v0.z = fmaf(GW0, t0.z, fmaf(GW1, t1.z, fmaf(GW2, t2.z, fmaf(GW1, t3.z, GW0 * t4.z))));
        v0.w = fmaf(GW0, t0.w, fmaf(GW1, t1.w, fmaf(GW2, t2.w, fmaf(GW1, t3.w, GW0 * t4.w))));
        v1.x = fmaf(GW0, t1.x, fmaf(GW1, t2.x, fmaf(GW2, t3.x, fmaf(GW1, t4.x, GW0 * t5.x))));
        v1.y = fmaf(GW0, t1.y, fmaf(GW1, t2.y, fmaf(GW2, t3.y, fmaf(GW1, t4.y, GW0 * t5.y))));
        v1.z = fmaf(GW0, t1.z, fmaf(GW1, t2.z, fmaf(GW2, t3.z, fmaf(GW1, t4.z, GW0 * t5.z))));
        v1.w = fmaf(GW0, t1.w, fmaf(GW1, t2.w, fmaf(GW2, t3.w, fmaf(GW1, t4.w, GW0 * t5.w))));

        // x-edge zero padding (sobel zero pad outside image)
        const int gx = mx0 - 1 + (j << 2);
        if (gx < 0 || gx >= IMG_W)  { v0.x = 0.f; v1.x = 0.f; }
        if (gx + 1 >= IMG_W)        { v0.y = 0.f; v1.y = 0.f; }
        if (gx + 2 >= IMG_W)        { v0.z = 0.f; v1.z = 0.f; }
        if (gx + 3 >= IMG_W)        { v0.w = 0.f; v1.w = 0.f; }
        // y-edge zero padding
        const int gy0 = my0 - 1 + (p << 1);
        if (gy0 < 0 || gy0 >= IMG_H) v0 = make_float4(0.f, 0.f, 0.f, 0.f);
        if (gy0 + 1 >= IMG_H)        v1 = make_float4(0.f, 0.f, 0.f, 0.f);

        *reinterpret_cast<float4*>(&sG[(p << 1) * SW + (j << 2)]) = v0;
        *reinterpret_cast<float4*>(&sG[((p << 1) + 1) * SW + (j << 2)]) = v1;
    }
    __syncthreads();

    // ---- Stage 4: sobel + magnitude + 4x4 avg pool + sigmoid^2 ----
    if (tid < TW * TH) {
        const int ty = tid / TW;
        const int tx = tid - ty * TW;
        const float* base = &sG[(ty << 2) * SW + (tx << 2)];

        float r0[6], r1[6], r2[6];
        {
            float4 L = *reinterpret_cast<const float4*>(base);
            float4 R = *reinterpret_cast<const float4*>(base + 4);
            r0[0]=L.x; r0[1]=L.y; r0[2]=L.z; r0[3]=L.w; r0[4]=R.x; r0[5]=R.y;
            L = *reinterpret_cast<const float4*>(base + SW);
            R = *reinterpret_cast<const float4*>(base + SW + 4);
            r1[0]=L.x; r1[1]=L.y; r1[2]=L.z; r1[3]=L.w; r1[4]=R.x; r1[5]=R.y;
        }

        float sum = 0.0f;
        #pragma unroll
        for (int r = 1; r <= 4; r++) {
            const float4 L = *reinterpret_cast<const float4*>(base + (r + 1) * SW);
            const float4 R = *reinterpret_cast<const float4*>(base + (r + 1) * SW + 4);
            r2[0]=L.x; r2[1]=L.y; r2[2]=L.z; r2[3]=L.w; r2[4]=R.x; r2[5]=R.y;

            float cv[6];
            #pragma unroll
            for (int c = 0; c < 6; c++) cv[c] = r0[c] + 2.0f * r1[c] + r2[c];

            #pragma unroll
            for (int c = 1; c <= 4; c++) {
                const float gx = cv[c + 1] - cv[c - 1];
                const float gy = (r2[c - 1] + 2.0f * r2[c] + r2[c + 1])
                               - (r0[c - 1] + 2.0f * r0[c] + r0[c + 1]);
                sum += sqrt_approx(fmaf(gx, gx, fmaf(gy, gy, 1e-6f)));
            }
            #pragma unroll
            for (int c = 0; c < 6; c++) { r0[c] = r1[c]; r1[c] = r2[c]; }
        }

        const float down = sum * (1.0f / 16.0f);
        const float e = __expf(-5.0f * (down - 0.2f));
        const float s = __fdividef(1.0f, 1.0f + e);
        const int oy = by * TH + ty;
        const int ox = bx * TW + tx;
        out[((size_t)b * OUT_H + oy) * OUT_W + ox] = s * s;
    }
}

extern "C" void kernel_launch(void* const* d_in, const int* in_sizes, int n_in,
                              void* d_out, int out_size)
{
    const float* in = (const float*)d_in[0];
    float* out = (float*)d_out;
    int B = in_sizes[0] / (3 * IMG_H * IMG_W);   // 16

    dim3 grid(OUT_W / TW, OUT_H / TH, B);        // (8, 17, 16) = 2176 blocks
    EdgeGuidance_47313359733145_kernel<<<grid, 256>>>(in, out);
}

// round 5
// speedup vs baseline: 1.9427x; 1.0502x over previous
#include <cuda_runtime.h>
#include <cuda_bf16.h>

// Fixed problem shapes
#define IMG_H 544
#define IMG_W 960
#define OUT_H 136
#define OUT_W 240

// Tile: 30x4 output pixels per block -> 120x16 mag region
#define TW 30
#define TH 4
#define MW 120
#define MH 16
#define GRH 22            // gray / h-blur rows (MH + 6)
#define GSH 18            // gray_smooth rows  (MH + 2)
#define SW 124            // smem stride in floats (31 float4)

// Normalized 1D Gaussian, k=5, sigma=1.5
#define GW0 0.120078385f
#define GW1 0.233880757f
#define GW2 0.292081718f

__device__ __forceinline__ int reflect_idx(int i, int n) {
    if (i < 0) i = -i;
    if (i >= n) i = 2 * n - 2 - i;
    return i;
}

__device__ __forceinline__ float sqrt_approx(float x) {
    float r;
    asm("sqrt.approx.f32 %0, %1;" : "=f"(r) : "f"(x));
    return r;
}

__global__ __launch_bounds__(256, 6)
void EdgeGuidance_47313359733145_kernel(const float* __restrict__ in,
                                        float* __restrict__ out)
{
    const int bx = blockIdx.x;            // 0..7
    const int by = blockIdx.y;            // 0..33
    const int b  = blockIdx.z;            // 0..15

    const int mx0 = bx * MW;
    const int my0 = by * MH;

    __shared__ float sH[GRH * SW];        // horizontal blur  (22x124)
    __shared__ float sG[GSH * SW];        // gray_smooth      (18x124)

    const int tid = threadIdx.x;
    const float* __restrict__ pr = in + (size_t)b * 3 * IMG_H * IMG_W;
    const float* __restrict__ pg = pr + IMG_H * IMG_W;
    const float* __restrict__ pb = pg + IMG_H * IMG_W;

    // ---- Stage 1+2 fused: RGB -> gray (registers) -> h-blur via warp shuffle ----
    // lane j = vec-column (0..31); gray local x = 4j covering global mx0-4+4j.
    #pragma unroll 1
    for (int i = tid; i < GRH * 32; i += 256) {
        const int y  = i >> 5;
        const int j  = i & 31;                        // == lane id
        const int gy = reflect_idx(my0 - 3 + y, IMG_H);
        const int gx0 = mx0 - 4 + (j << 2);

        float4 r4, g4, b4;
        if (gx0 >= 0 && gx0 + 3 < IMG_W) {
            const int o = gy * IMG_W + gx0;
            r4 = *reinterpret_cast<const float4*>(pr + o);
            g4 = *reinterpret_cast<const float4*>(pg + o);
            b4 = *reinterpret_cast<const float4*>(pb + o);
        } else {
            float rr[4], gg[4], bb[4];
            #pragma unroll
            for (int e = 0; e < 4; e++) {
                int gx = reflect_idx(gx0 + e, IMG_W);
                int o = gy * IMG_W + gx;
                rr[e] = pr[o]; gg[e] = pg[o]; bb[e] = pb[o];
            }
            r4 = make_float4(rr[0], rr[1], rr[2], rr[3]);
            g4 = make_float4(gg[0], gg[1], gg[2], gg[3]);
            b4 = make_float4(bb[0], bb[1], bb[2], bb[3]);
        }
        float4 A;
        A.x = fmaf(0.2989f, r4.x, fmaf(0.587f, g4.x, 0.114f * b4.x));
        A.y = fmaf(0.2989f, r4.y, fmaf(0.587f, g4.y, 0.114f * b4.y));
        A.z = fmaf(0.2989f, r4.z, fmaf(0.587f, g4.z, 0.114f * b4.z));
        A.w = fmaf(0.2989f, r4.w, fmaf(0.587f, g4.w, 0.114f * b4.w));

        const unsigned m = 0xffffffffu;
        const float Bx = __shfl_down_sync(m, A.x, 1);
        const float By = __shfl_down_sync(m, A.y, 1);
        const float Bz = __shfl_down_sync(m, A.z, 1);
        const float Bw = __shfl_down_sync(m, A.w, 1);
        const float C0 = __shfl_down_sync(m, A.x, 2);

        if (j < 31) {
            float4 o4;
            o4.x = fmaf(GW0, A.y, fmaf(GW1, A.z, fmaf(GW2, A.w, fmaf(GW1, Bx, GW0 * By))));
            o4.y = fmaf(GW0, A.z, fmaf(GW1, A.w, fmaf(GW2, Bx, fmaf(GW1, By, GW0 * Bz))));
            o4.z = fmaf(GW0, A.w, fmaf(GW1, Bx, fmaf(GW2, By, fmaf(GW1, Bz, GW0 * Bw))));
            o4.w = fmaf(GW0, Bx, fmaf(GW1, By, fmaf(GW2, Bz, fmaf(GW1, Bw, GW0 * C0))));
            *reinterpret_cast<float4*>(&sH[y * SW + (j << 2)]) = o4;
        }
    }
    __syncthreads();

    // ---- Stage 3: vertical Gaussian, two rows per thread (6 loads -> 2 outputs) ----
    // 9 row-pairs (18 gs rows), 31 active vec-cols
    #pragma unroll 1
    for (int i = tid; i < 9 * 32; i += 256) {
        const int p = i >> 5;
        const int j = i & 31;
        if (j >= 31) continue;
        const float* c = &sH[(p << 1) * SW + (j << 2)];
        const float4 t0 = *reinterpret_cast<const float4*>(c);
        const float4 t1 = *reinterpret_cast<const float4*>(c + SW);
        const float4 t2 = *reinterpret_cast<const float4*>(c + 2 * SW);
        const float4 t3 = *reinterpret_cast<const float4*>(c + 3 * SW);
        const float4 t4 = *reinterpret_cast<const float4*>(c + 4 * SW);
        const float4 t5 = *reinterpret_cast<const float4*>(c + 5 * SW);

        float4 v0, v1;
        v0.x = fmaf(GW0, t0.x, fmaf(GW1, t1.x, fmaf(GW2, t2.x, fmaf(GW1, t3.x, GW0 * t4.x))));
        v0.y = fmaf(GW0, t0.y, fmaf(GW1, t1.y, fmaf(GW2, t2.y, fmaf(GW1, t3.y, GW0 * t4.y))));
        v0.z = fmaf(GW0, t0.z, fmaf(GW1, t1.z, fmaf(GW2, t2.z, fmaf(GW1, t3.z, GW0 * t4.z))));
        v0.w = fmaf(GW0, t0.w, fmaf(GW1, t1.w, fmaf(GW2, t2.w, fmaf(GW1, t3.w, GW0 * t4.w))));
        v1.x = fmaf(GW0, t1.x, fmaf(GW1, t2.x, fmaf(GW2, t3.x, fmaf(GW1, t4.x, GW0 * t5.x))));
        v1.y = fmaf(GW0, t1.y, fmaf(GW1, t2.y, fmaf(GW2, t3.y, fmaf(GW1, t4.y, GW0 * t5.y))));
        v1.z = fmaf(GW0, t1.z, fmaf(GW1, t2.z, fmaf(GW2, t3.z, fmaf(GW1, t4.z, GW0 * t5.z))));
        v1.w = fmaf(GW0, t1.w, fmaf(GW1, t2.w, fmaf(GW2, t3.w, fmaf(GW1, t4.w, GW0 * t5.w))));

        // x-edge zero padding (sobel zero pad outside image)
        const int gx = mx0 - 1 + (j << 2);
        if (gx < 0 || gx >= IMG_W)  { v0.x = 0.f; v1.x = 0.f; }
        if (gx + 1 >= IMG_W)        { v0.y = 0.f; v1.y = 0.f; }
        if (gx + 2 >= IMG_W)        { v0.z = 0.f; v1.z = 0.f; }
        if (gx + 3 >= IMG_W)        { v0.w = 0.f; v1.w = 0.f; }
        // y-edge zero padding
        const int gy0 = my0 - 1 + (p << 1);
        if (gy0 < 0 || gy0 >= IMG_H) v0 = make_float4(0.f, 0.f, 0.f, 0.f);
        if (gy0 + 1 >= IMG_H)        v1 = make_float4(0.f, 0.f, 0.f, 0.f);

        *reinterpret_cast<float4*>(&sG[(p << 1) * SW + (j << 2)]) = v0;
        *reinterpret_cast<float4*>(&sG[((p << 1) + 1) * SW + (j << 2)]) = v1;
    }
    __syncthreads();

    // ---- Stage 4: sobel + magnitude + 4x4 avg pool + sigmoid^2 ----
    if (tid < TW * TH) {
        const int ty = tid / TW;              // 0..3
        const int tx = tid - ty * TW;         // 0..29
        const float* base = &sG[(ty << 2) * SW + (tx << 2)];

        float r0[6], r1[6], r2[6];
        {
            float4 L = *reinterpret_cast<const float4*>(base);
            float4 R = *reinterpret_cast<const float4*>(base + 4);
            r0[0]=L.x; r0[1]=L.y; r0[2]=L.z; r0[3]=L.w; r0[4]=R.x; r0[5]=R.y;
            L = *reinterpret_cast<const float4*>(base + SW);
            R = *reinterpret_cast<const float4*>(base + SW + 4);
            r1[0]=L.x; r1[1]=L.y; r1[2]=L.z; r1[3]=L.w; r1[4]=R.x; r1[5]=R.y;
        }

        float sum = 0.0f;
        #pragma unroll
        for (int r = 1; r <= 4; r++) {
            const float4 L = *reinterpret_cast<const float4*>(base + (r + 1) * SW);
            const float4 R = *reinterpret_cast<const float4*>(base + (r + 1) * SW + 4);
            r2[0]=L.x; r2[1]=L.y; r2[2]=L.z; r2[3]=L.w; r2[4]=R.x; r2[5]=R.y;

            float cv[6];
            #pragma unroll
            for (int c = 0; c < 6; c++) cv[c] = r0[c] + 2.0f * r1[c] + r2[c];

            #pragma unroll
            for (int c = 1; c <= 4; c++) {
                const float gx = cv[c + 1] - cv[c - 1];
                const float gy = (r2[c - 1] + 2.0f * r2[c] + r2[c + 1])
                               - (r0[c - 1] + 2.0f * r0[c] + r0[c + 1]);
                sum += sqrt_approx(fmaf(gx, gx, fmaf(gy, gy, 1e-6f)));
            }
            #pragma unroll
            for (int c = 0; c < 6; c++) { r0[c] = r1[c]; r1[c] = r2[c]; }
        }

        const float down = sum * (1.0f / 16.0f);
        const float e = __expf(-5.0f * (down - 0.2f));
        const float s = __fdividef(1.0f, 1.0f + e);
        const int oy = by * TH + ty;
        const int ox = bx * TW + tx;
        out[((size_t)b * OUT_H + oy) * OUT_W + ox] = s * s;
    }
}

extern "C" void kernel_launch(void* const* d_in, const int* in_sizes, int n_in,
                              void* d_out, int out_size)
{
    const float* in = (const float*)d_in[0];
    float* out = (float*)d_out;
    int B = in_sizes[0] / (3 * IMG_H * IMG_W);   // 16

    dim3 grid(OUT_W / TW, OUT_H / TH, B);        // (8, 34, 16) = 4352 blocks
    EdgeGuidance_47313359733145_kernel<<<grid, 256>>>(in, out);
}

// round 6
// speedup vs baseline: 2.1183x; 1.0904x over previous
#include <cuda_runtime.h>
#include <cuda_bf16.h>

// Fixed problem shapes
#define IMG_H 544
#define IMG_W 960
#define OUT_H 136
#define OUT_W 240

// Each WARP produces a 30x4 output strip (120x16 mag region) by streaming
// 22 input rows with all intermediates in registers (no shared memory).
#define TW 30

// Normalized 1D Gaussian, k=5, sigma=1.5
#define GW0 0.120078385f
#define GW1 0.233880757f
#define GW2 0.292081718f

__device__ __forceinline__ int reflect_idx(int i, int n) {
    if (i < 0) i = -i;
    if (i >= n) i = 2 * n - 2 - i;
    return i;
}

__device__ __forceinline__ float sqrt_approx(float x) {
    float r;
    asm("sqrt.approx.f32 %0, %1;" : "=f"(r) : "f"(x));
    return r;
}

__global__ __launch_bounds__(128, 8)
void EdgeGuidance_47313359733145_kernel(const float* __restrict__ in,
                                        float* __restrict__ out)
{
    const int lane = threadIdx.x & 31;
    const int wid  = threadIdx.x >> 5;
    const int ct   = blockIdx.x * 4 + wid;   // column tile 0..7  (30 out cols each)
    const int by   = blockIdx.y;             // row strip 0..33   (4 out rows each)
    const int b    = blockIdx.z;             // batch

    const int mx0 = ct * (TW * 4);           // mag-space x origin (120 per tile)
    const int my0 = by * 16;                 // mag-space y origin

    const float* __restrict__ pr = in + (size_t)b * 3 * IMG_H * IMG_W;
    const float* __restrict__ pg = pr + IMG_H * IMG_W;
    const float* __restrict__ pb = pg + IMG_H * IMG_W;

    // Lane's gray vec covers global x = gx0 .. gx0+3
    const int gx0 = mx0 - 4 + (lane << 2);
    const bool xfast = (gx0 >= 0) && (gx0 + 3 < IMG_W);
    // Precomputed reflected x indices for the slow path (only edge lanes use them)
    int rx0 = reflect_idx(gx0 + 0, IMG_W);
    int rx1 = reflect_idx(gx0 + 1, IMG_W);
    int rx2 = reflect_idx(gx0 + 2, IMG_W);
    int rx3 = reflect_idx(gx0 + 3, IMG_W);

    // gs vec of this lane covers global x = gsx .. gsx+3  (gs local p <-> mx0-1+p)
    const int gsx = mx0 - 1 + (lane << 2);
    const bool vx0 = (gsx + 0 >= 0) && (gsx + 0 < IMG_W);
    const bool vx1 = (gsx + 1 >= 0) && (gsx + 1 < IMG_W);
    const bool vx2 = (gsx + 2 < IMG_W);
    const bool vx3 = (gsx + 3 < IMG_W);

    const unsigned FULL = 0xffffffffu;

    // h-blur of input row t (t = 0..21, global row = reflect(my0-3+t)).
    // Returns the lane's h-blurred vec at gs locals 4*lane .. 4*lane+3.
    auto hbrow = [&](int t) -> float4 {
        const int gy = reflect_idx(my0 - 3 + t, IMG_H);
        const int rowoff = gy * IMG_W;
        float4 r4, g4, b4;
        if (xfast) {
            r4 = *reinterpret_cast<const float4*>(pr + rowoff + gx0);
            g4 = *reinterpret_cast<const float4*>(pg + rowoff + gx0);
            b4 = *reinterpret_cast<const float4*>(pb + rowoff + gx0);
        } else {
            r4 = make_float4(pr[rowoff + rx0], pr[rowoff + rx1], pr[rowoff + rx2], pr[rowoff + rx3]);
            g4 = make_float4(pg[rowoff + rx0], pg[rowoff + rx1], pg[rowoff + rx2], pg[rowoff + rx3]);
            b4 = make_float4(pb[rowoff + rx0], pb[rowoff + rx1], pb[rowoff + rx2], pb[rowoff + rx3]);
        }
        float4 A;
        A.x = fmaf(0.2989f, r4.x, fmaf(0.587f, g4.x, 0.114f * b4.x));
        A.y = fmaf(0.2989f, r4.y, fmaf(0.587f, g4.y, 0.114f * b4.y));
        A.z = fmaf(0.2989f, r4.z, fmaf(0.587f, g4.z, 0.114f * b4.z));
        A.w = fmaf(0.2989f, r4.w, fmaf(0.587f, g4.w, 0.114f * b4.w));

        const float Bx = __shfl_down_sync(FULL, A.x, 1);
        const float By = __shfl_down_sync(FULL, A.y, 1);
        const float Bz = __shfl_down_sync(FULL, A.z, 1);
        const float Bw = __shfl_down_sync(FULL, A.w, 1);
        const float C0 = __shfl_down_sync(FULL, A.x, 2);

        float4 o4;
        o4.x = fmaf(GW0, A.y, fmaf(GW1, A.z, fmaf(GW2, A.w, fmaf(GW1, Bx, GW0 * By))));
        o4.y = fmaf(GW0, A.z, fmaf(GW1, A.w, fmaf(GW2, Bx, fmaf(GW1, By, GW0 * Bz))));
        o4.z = fmaf(GW0, A.w, fmaf(GW1, Bx, fmaf(GW2, By, fmaf(GW1, Bz, GW0 * Bw))));
        o4.w = fmaf(GW0, Bx, fmaf(GW1, By, fmaf(GW2, Bz, fmaf(GW1, Bw, GW0 * C0))));
        return o4;
    };

    // Rolling h-blur window: hb[0..3] = input rows r..r+3 at the start of iter r
    float4 hb0 = hbrow(0);
    float4 hb1 = hbrow(1);
    float4 hb2 = hbrow(2);
    float4 hb3 = hbrow(3);

    // Rolling gs window rows (6 floats: own vec + next lane's first two)
    float w0[6], w1[6], w2[6];
    float acc = 0.0f;

    const size_t outbase = ((size_t)b * OUT_H + by * 4) * OUT_W + ct * TW + lane;

    #pragma unroll
    for (int r = 0; r < 18; ++r) {
        const float4 h4 = hbrow(r + 4);

        // Vertical Gaussian -> gs row r (global gy = my0-1+r)
        float4 g;
        g.x = fmaf(GW0, hb0.x, fmaf(GW1, hb1.x, fmaf(GW2, hb2.x, fmaf(GW1, hb3.x, GW0 * h4.x))));
        g.y = fmaf(GW0, hb0.y, fmaf(GW1, hb1.y, fmaf(GW2, hb2.y, fmaf(GW1, hb3.y, GW0 * h4.y))));
        g.z = fmaf(GW0, hb0.z, fmaf(GW1, hb1.z, fmaf(GW2, hb2.z, fmaf(GW1, hb3.z, GW0 * h4.z))));
        g.w = fmaf(GW0, hb0.w, fmaf(GW1, hb1.w, fmaf(GW2, hb2.w, fmaf(GW1, hb3.w, GW0 * h4.w))));

        const int gy = my0 - 1 + r;
        const bool yok = (gy >= 0) && (gy < IMG_H);
        g.x = (yok && vx0) ? g.x : 0.0f;
        g.y = (yok && vx1) ? g.y : 0.0f;
        g.z = (yok && vx2) ? g.z : 0.0f;
        g.w = (yok && vx3) ? g.w : 0.0f;

        w2[0] = g.x; w2[1] = g.y; w2[2] = g.z; w2[3] = g.w;
        w2[4] = __shfl_down_sync(FULL, g.x, 1);
        w2[5] = __shfl_down_sync(FULL, g.y, 1);

        if (r >= 2) {
            // Sobel + magnitude for mag row m = r-2 (uses gs rows r-2, r-1, r)
            float cv[6];
            #pragma unroll
            for (int c = 0; c < 6; c++) cv[c] = w0[c] + 2.0f * w1[c] + w2[c];

            #pragma unroll
            for (int c = 1; c <= 4; c++) {
                const float sgx = cv[c + 1] - cv[c - 1];
                const float sgy = (w2[c - 1] + 2.0f * w2[c] + w2[c + 1])
                                - (w0[c - 1] + 2.0f * w0[c] + w0[c + 1]);
                acc += sqrt_approx(fmaf(sgx, sgx, fmaf(sgy, sgy, 1e-6f)));
            }

            if (((r - 2) & 3) == 3) {       // r = 5, 9, 13, 17
                const float down = acc * (1.0f / 16.0f);
                const float e = __expf(-5.0f * (down - 0.2f));
                const float s = __fdividef(1.0f, 1.0f + e);
                if (lane < TW) {
                    out[outbase + (size_t)((r - 5) >> 2) * OUT_W] = s * s;
                }
                acc = 0.0f;
            }
        }

        // Shift windows (register renames under full unroll)
        hb0 = hb1; hb1 = hb2; hb2 = hb3; hb3 = h4;
        #pragma unroll
        for (int c = 0; c < 6; c++) { w0[c] = w1[c]; w1[c] = w2[c]; }
    }
}

extern "C" void kernel_launch(void* const* d_in, const int* in_sizes, int n_in,
                              void* d_out, int out_size)
{
    const float* in = (const float*)d_in[0];
    float* out = (float*)d_out;

    // 8 col tiles (4 per block) x 34 row strips x 16 batch
    dim3 grid(2, 34, 16);                    // 1088 blocks of 128 threads
    EdgeGuidance_47313359733145_kernel<<<grid, 128>>>(in, out);
}

// round 7
// speedup vs baseline: 2.2251x; 1.0504x over previous
#include <cuda_runtime.h>
#include <cuda_bf16.h>

// Fixed problem shapes
#define IMG_H 544
#define IMG_W 960
#define OUT_H 136
#define OUT_W 240

// Each WARP produces a 30x8 output strip (120x32 mag region) by streaming
// 38 input rows with all intermediates in registers (no shared memory).
// Depth-2 row prefetch through a 3-slot raw RGB ring buffer.
#define TW 30

// Normalized 1D Gaussian, k=5, sigma=1.5
#define GW0 0.120078385f
#define GW1 0.233880757f
#define GW2 0.292081718f

__device__ __forceinline__ int reflect_idx(int i, int n) {
    if (i < 0) i = -i;
    if (i >= n) i = 2 * n - 2 - i;
    return i;
}

__device__ __forceinline__ float sqrt_approx(float x) {
    float r;
    asm("sqrt.approx.f32 %0, %1;" : "=f"(r) : "f"(x));
    return r;
}

__global__ __launch_bounds__(128, 4)
void EdgeGuidance_47313359733145_kernel(const float* __restrict__ in,
                                        float* __restrict__ out)
{
    const int lane = threadIdx.x & 31;
    const int wid  = threadIdx.x >> 5;
    const int ct   = blockIdx.x * 4 + wid;   // column tile 0..7 (30 out cols each)
    const int by   = blockIdx.y;             // row strip 0..16  (8 out rows each)
    const int b    = blockIdx.z;             // batch

    const int mx0 = ct * (TW * 4);           // mag-space x origin (120 per tile)
    const int my0 = by * 32;                 // mag-space y origin

    const float* __restrict__ pr = in + (size_t)b * 3 * IMG_H * IMG_W;
    const float* __restrict__ pg = pr + IMG_H * IMG_W;
    const float* __restrict__ pb = pg + IMG_H * IMG_W;

    // Lane's gray vec covers global x = gx0 .. gx0+3
    const int gx0 = mx0 - 4 + (lane << 2);
    const bool xfast = (gx0 >= 0) && (gx0 + 3 < IMG_W);
    const int rx0 = reflect_idx(gx0 + 0, IMG_W);
    const int rx1 = reflect_idx(gx0 + 1, IMG_W);
    const int rx2 = reflect_idx(gx0 + 2, IMG_W);
    const int rx3 = reflect_idx(gx0 + 3, IMG_W);

    // gs vec of this lane covers global x = gsx .. gsx+3
    const int gsx = mx0 - 1 + (lane << 2);
    const bool vx0 = (gsx + 0 >= 0) && (gsx + 0 < IMG_W);
    const bool vx1 = (gsx + 1 >= 0) && (gsx + 1 < IMG_W);
    const bool vx2 = (gsx + 2 < IMG_W);
    const bool vx3 = (gsx + 3 < IMG_W);

    const unsigned FULL = 0xffffffffu;

    // 3-slot raw RGB ring buffer (depth-2 prefetch)
    float4 RB[3], GB[3], BB[3];

    // Issue loads for input row t into slot s. t = 0..37, global row = reflect(my0-3+t).
    auto loadraw = [&](int t, int s) {
        const int gy = reflect_idx(my0 - 3 + t, IMG_H);
        const int rowoff = gy * IMG_W;
        if (xfast) {
            RB[s] = *reinterpret_cast<const float4*>(pr + rowoff + gx0);
            GB[s] = *reinterpret_cast<const float4*>(pg + rowoff + gx0);
            BB[s] = *reinterpret_cast<const float4*>(pb + rowoff + gx0);
        } else {
            RB[s] = make_float4(pr[rowoff + rx0], pr[rowoff + rx1], pr[rowoff + rx2], pr[rowoff + rx3]);
            GB[s] = make_float4(pg[rowoff + rx0], pg[rowoff + rx1], pg[rowoff + rx2], pg[rowoff + rx3]);
            BB[s] = make_float4(pb[rowoff + rx0], pb[rowoff + rx1], pb[rowoff + rx2], pb[rowoff + rx3]);
        }
    };

    // gray conversion + horizontal blur (shuffle-based) of slot s
    auto gb = [&](int s) -> float4 {
        const float4 r4 = RB[s], g4 = GB[s], b4 = BB[s];
        float4 A;
        A.x = fmaf(0.2989f, r4.x, fmaf(0.587f, g4.x, 0.114f * b4.x));
        A.y = fmaf(0.2989f, r4.y, fmaf(0.587f, g4.y, 0.114f * b4.y));
        A.z = fmaf(0.2989f, r4.z, fmaf(0.587f, g4.z, 0.114f * b4.z));
        A.w = fmaf(0.2989f, r4.w, fmaf(0.587f, g4.w, 0.114f * b4.w));

        const float Bx = __shfl_down_sync(FULL, A.x, 1);
        const float By = __shfl_down_sync(FULL, A.y, 1);
        const float Bz = __shfl_down_sync(FULL, A.z, 1);
        const float Bw = __shfl_down_sync(FULL, A.w, 1);
        const float C0 = __shfl_down_sync(FULL, A.x, 2);

        float4 o4;
        o4.x = fmaf(GW0, A.y, fmaf(GW1, A.z, fmaf(GW2, A.w, fmaf(GW1, Bx, GW0 * By))));
        o4.y = fmaf(GW0, A.z, fmaf(GW1, A.w, fmaf(GW2, Bx, fmaf(GW1, By, GW0 * Bz))));
        o4.z = fmaf(GW0, A.w, fmaf(GW1, Bx, fmaf(GW2, By, fmaf(GW1, Bz, GW0 * Bw))));
        o4.w = fmaf(GW0, Bx, fmaf(GW1, By, fmaf(GW2, Bz, fmaf(GW1, Bw, GW0 * C0))));
        return o4;
    };

    // Prologue: fill ring (rows 0..2), then h-blur rows 0..3 while loading 3..6.
    loadraw(0, 0); loadraw(1, 1); loadraw(2, 2);
    float4 hb0 = gb(0); loadraw(3, 0);
    float4 hb1 = gb(1); loadraw(4, 1);
    float4 hb2 = gb(2); loadraw(5, 2);
    float4 hb3 = gb(0); loadraw(6, 0);
    // Invariant at iter r: raw(r+4) in slot (r+1)%3; raw(r+5), raw(r+6) in flight.

    float w0[6], w1[6], w2[6];
    float acc = 0.0f;

    const size_t outbase = ((size_t)b * OUT_H + by * 8) * OUT_W + ct * TW + lane;

    #pragma unroll
    for (int r = 0; r < 34; ++r) {
        const int s = (r + 1) % 3;           // compile-time under full unroll
        const float4 h4 = gb(s);             // consume raw(r+4)
        if (r + 7 <= 37) loadraw(r + 7, s);  // refill slot (keeps depth 2)

        // Vertical Gaussian -> gs row r (global gy = my0-1+r)
        float4 g;
        g.x = fmaf(GW0, hb0.x, fmaf(GW1, hb1.x, fmaf(GW2, hb2.x, fmaf(GW1, hb3.x, GW0 * h4.x))));
        g.y = fmaf(GW0, hb0.y, fmaf(GW1, hb1.y, fmaf(GW2, hb2.y, fmaf(GW1, hb3.y, GW0 * h4.y))));
        g.z = fmaf(GW0, hb0.z, fmaf(GW1, hb1.z, fmaf(GW2, hb2.z, fmaf(GW1, hb3.z, GW0 * h4.z))));
        g.w = fmaf(GW0, hb0.w, fmaf(GW1, hb1.w, fmaf(GW2, hb2.w, fmaf(GW1, hb3.w, GW0 * h4.w))));

        const int gy = my0 - 1 + r;
        const bool yok = (gy >= 0) && (gy < IMG_H);
        g.x = (yok && vx0) ? g.x : 0.0f;
        g.y = (yok && vx1) ? g.y : 0.0f;
        g.z = (yok && vx2) ? g.z : 0.0f;
        g.w = (yok && vx3) ? g.w : 0.0f;

        w2[0] = g.x; w2[1] = g.y; w2[2] = g.z; w2[3] = g.w;
        w2[4] = __shfl_down_sync(FULL, g.x, 1);
        w2[5] = __shfl_down_sync(FULL, g.y, 1);

        if (r >= 2) {
            // Sobel + magnitude for mag row m = r-2 (uses gs rows r-2, r-1, r)
            float cv[6];
            #pragma unroll
            for (int c = 0; c < 6; c++) cv[c] = w0[c] + 2.0f * w1[c] + w2[c];

            #pragma unroll
            for (int c = 1; c <= 4; c++) {
                const float sgx = cv[c + 1] - cv[c - 1];
                const float sgy = (w2[c - 1] + 2.0f * w2[c] + w2[c + 1])
                                - (w0[c - 1] + 2.0f * w0[c] + w0[c + 1]);
                acc += sqrt_approx(fmaf(sgx, sgx, fmaf(sgy, sgy, 1e-6f)));
            }

            if (((r - 2) & 3) == 3) {        // r = 5, 9, ..., 33 -> 8 output rows
                const float down = acc * (1.0f / 16.0f);
                const float e = __expf(-5.0f * (down - 0.2f));
                const float sg = __fdividef(1.0f, 1.0f + e);
                if (lane < TW) {
                    out[outbase + (size_t)((r - 5) >> 2) * OUT_W] = sg * sg;
                }
                acc = 0.0f;
            }
        }

        // Shift windows (register renames under full unroll)
        hb0 = hb1; hb1 = hb2; hb2 = hb3; hb3 = h4;
        #pragma unroll
        for (int c = 0; c < 6; c++) { w0[c] = w1[c]; w1[c] = w2[c]; }
    }
}

extern "C" void kernel_launch(void* const* d_in, const int* in_sizes, int n_in,
                              void* d_out, int out_size)
{
    const float* in = (const float*)d_in[0];
    float* out = (float*)d_out;

    // 8 col tiles (4 warps per block) x 17 row strips x 16 batch
    dim3 grid(2, 17, 16);                    // 544 blocks of 128 threads
    EdgeGuidance_47313359733145_kernel<<<grid, 128>>>(in, out);
}